// round 12
// baseline (speedup 1.0000x reference)
#include <cuda_runtime.h>
#include <cuda_fp16.h>

#define IMG_H 512
#define IMG_W 512
#define HW (IMG_H * IMG_W)

// Channel-last, z-innermost fp16 staging: [b][y][x][z][32c]  (1 MB each).
// Each xy-corner owns a contiguous 512B block of 8 z-slots x 64B, so
// z-divergent lanes in a warp hit the same 4 cache lines instead of
// 16KB-apart planes.
__device__ __half g1h[8 * 16 * 16 * 8 * 32];
__device__ __half g2h[8 * 16 * 16 * 8 * 32];   // 27 real channels + 5 zero pad

__global__ __launch_bounds__(256) void transpose_grids_h(
    const float* __restrict__ g1, const float* __restrict__ g2)
{
    const int i = blockIdx.x * 256 + threadIdx.x;
    if (i < 8 * 32 * 8 * 256) {
        const int x = i & 15, y = (i >> 4) & 15, z = (i >> 8) & 7;
        const int c = (i >> 11) & 31, b = i >> 16;
        g1h[(((b * 256 + y * 16 + x) * 8) + z) * 32 + c] = __float2half(g1[i]);
    }
    if (i < 8 * 27 * 8 * 256) {
        const int x = i & 15, y = (i >> 4) & 15, z = (i >> 8) & 7;
        const int t = i >> 11;
        const int c = t % 27, b = t / 27;
        g2h[(((b * 256 + y * 16 + x) * 8) + z) * 32 + c] = __float2half(g2[i]);
    }
    if (i < 8 * 8 * 256) {   // pad channels 27..31 at every (b,y,x,z) slot
#pragma unroll
        for (int c = 27; c < 32; c++) g2h[i * 32 + c] = __float2half(0.0f);
    }
}

__device__ __forceinline__ float tanh_approx(float x) {
    float y;
    asm("tanh.approx.f32 %0, %1;" : "=f"(y) : "f"(x));
    return y;
}
typedef unsigned long long u64;
__device__ __forceinline__ u64 pk2(float lo, float hi) {
    u64 r;
    asm("mov.b64 %0, {%1, %2};" : "=l"(r) : "f"(lo), "f"(hi));
    return r;
}
__device__ __forceinline__ void upk2(float& lo, float& hi, u64 p) {
    asm("mov.b64 {%0, %1}, %2;" : "=f"(lo), "=f"(hi) : "l"(p));
}
__device__ __forceinline__ u64 fma2q(u64 a, u64 b, u64 c) {
    u64 d;
    asm("fma.rn.f32x2 %0, %1, %2, %3;" : "=l"(d) : "l"(a), "l"(b), "l"(c));
    return d;
}
__device__ __forceinline__ u64 add2q(u64 a, u64 b) {
    u64 d;
    asm("add.rn.f32x2 %0, %1, %2;" : "=l"(d) : "l"(a), "l"(b));
    return d;
}
__device__ __forceinline__ u64 h2f2(__half2 h) {
    u64 r;
    unsigned int u = *(unsigned int*)&h;
    asm("{\n\t.reg .b16 l, h;\n\t.reg .f32 fl, fh;\n\t"
        "mov.b32 {l, h}, %1;\n\t"
        "cvt.f32.f16 fl, l;\n\t"
        "cvt.f32.f16 fh, h;\n\t"
        "mov.b64 %0, {fl, fh};\n\t}" : "=l"(r) : "r"(u));
    return r;
}
__device__ __forceinline__ __half2 u2h(unsigned int u) { return *(__half2*)&u; }

// bilinear (fp16, near-exact weights) at z0 and z1, then z-lerp in f32x2.
__device__ __forceinline__ u64 xyz_interp(
    unsigned a00, unsigned a01, unsigned a10, unsigned a11,
    unsigned b00, unsigned b01, unsigned b10, unsigned b11,
    __half2 w00h, __half2 w01h, __half2 w10h, __half2 w11h, u64 wzq)
{
    __half2 s0 = __hmul2(w00h, u2h(a00));
    s0 = __hfma2(w01h, u2h(a01), s0);
    s0 = __hfma2(w10h, u2h(a10), s0);
    s0 = __hfma2(w11h, u2h(a11), s0);
    __half2 s1 = __hmul2(w00h, u2h(b00));
    s1 = __hfma2(w01h, u2h(b01), s1);
    s1 = __hfma2(w10h, u2h(b10), s1);
    s1 = __hfma2(w11h, u2h(b11), s1);
    const u64 A = h2f2(s0);
    const u64 B = h2f2(s1);
    const u64 d = add2q(B, A ^ 0x8000000080000000ULL);  // exact B - A
    return fma2q(wzq, d, A);                            // A + wz*(B-A), wz fp32
}

__global__ __launch_bounds__(256, 4) void bgrid_fused_kernel(
    const float* __restrict__ src,
    const float* __restrict__ w1, const float* __restrict__ b1,
    const float* __restrict__ w2, const float* __restrict__ b2,
    const float* __restrict__ w3, const float* __restrict__ b3,
    const float* __restrict__ w4, const float* __restrict__ b4,
    float* __restrict__ out)
{
    __shared__ float2 sp1[8][3];
    __shared__ float2 b1p[8];
    __shared__ float  sw2[16];
    __shared__ float2 sp3[8][8];
    __shared__ float2 b3p[8];
    __shared__ float  sw4[16];
    __shared__ float  sb2s, sb4s;

    const int tid = threadIdx.x;
    if (tid < 24) {
        const int op = tid / 3, jj = tid - op * 3;
        sp1[op][jj] = make_float2(w1[(2 * op) * 3 + jj], w1[(2 * op + 1) * 3 + jj]);
    }
    if (tid < 8) {
        b1p[tid] = make_float2(b1[2 * tid], b1[2 * tid + 1]);
        b3p[tid] = make_float2(b3[2 * tid], b3[2 * tid + 1]);
    }
    if (tid < 16) { sw2[tid] = w2[tid]; sw4[tid] = w4[tid]; }
    if (tid < 64) {
        const int op = tid >> 3, q = tid & 7;
        sp3[op][q] = make_float2(w3[(2 * op) * 8 + q], w3[(2 * op + 1) * 8 + q]);
    }
    if (tid == 0) { sb2s = b2[0]; sb4s = b4[0]; }
    __syncthreads();

    const int idx = blockIdx.x * 256 + tid;
    const int px = idx & 511;
    const int py = (idx >> 9) & 511;
    const int pb = idx >> 18;

    // ---- src pixel ----
    const float* srcp = src + (pb * 3) * HW + py * IMG_W + px;
    const float s0 = srcp[0];
    const float s1 = srcp[HW];
    const float s2 = srcp[2 * HW];
    const u64 sap[4] = {pk2(s0, s0), pk2(s1, s1), pk2(s2, s2), pk2(1.0f, 1.0f)};

    // ---- guide NN #1 ----
    float g = sb2s;
#pragma unroll
    for (int op = 0; op < 8; op++) {
        u64 t2 = *(const u64*)&b1p[op];
        t2 = fma2q(sap[0], *(const u64*)&sp1[op][0], t2);
        t2 = fma2q(sap[1], *(const u64*)&sp1[op][1], t2);
        t2 = fma2q(sap[2], *(const u64*)&sp1[op][2], t2);
        float lo, hi; upk2(lo, hi, t2);
        lo = fmaxf(lo, 0.0f); hi = fmaxf(hi, 0.0f);
        g = fmaf(sw2[2 * op], lo, g);
        g = fmaf(sw2[2 * op + 1], hi, g);
    }
    g = tanh_approx(g);

    // ---- xy lattice: wx, wy exact multiples of 1/512 ----
    const float fx = (float)px * (15.0f / 512.0f);
    const float fy = (float)py * (15.0f / 512.0f);
    const int x0 = (int)fx;
    const int y0 = (int)fy;
    const float wx = fx - (float)x0;
    const float wy = fy - (float)y0;
    const __half2 w00h = __float2half2_rn((1.0f - wy) * (1.0f - wx));
    const __half2 w01h = __float2half2_rn((1.0f - wy) * wx);
    const __half2 w10h = __float2half2_rn(wy * (1.0f - wx));
    const __half2 w11h = __float2half2_rn(wy * wx);

    // corner bases in halves: [y][x] stride 256, y stride 4096
    const __half* gb1 = g1h + pb * 65536;
    const int ob00 = (y0 * 16 + x0) * 256;
    const int ob01 = ob00 + 256;
    const int ob10 = ob00 + 4096;
    const int ob11 = ob00 + 4352;

    // ---- z for slice 1 ----
    float fz = fminf(fmaxf((g + 1.0f) * 3.5f, 0.0f), 7.0f);
    int z0 = (int)fz;
    if (z0 > 7) z0 = 7;
    int z1 = min(z0 + 1, 7);
    u64 wzq = pk2(fz - (float)z0, fz - (float)z0);

    // ---- slice grid1 -> hidp[4] ----
    u64 hidp[4];
#pragma unroll
    for (int e = 0; e < 4; e++) hidp[e] = pk2(0.0f, 0.0f);
    {
        const int zo0 = z0 * 32, zo1 = z1 * 32;   // z-innermost: 64B per z slot
#pragma unroll
        for (int j = 0; j < 4; j++) {
            const uint4 a00 = __ldg((const uint4*)(gb1 + ob00 + zo0) + j);
            const uint4 a01 = __ldg((const uint4*)(gb1 + ob01 + zo0) + j);
            const uint4 a10 = __ldg((const uint4*)(gb1 + ob10 + zo0) + j);
            const uint4 a11 = __ldg((const uint4*)(gb1 + ob11 + zo0) + j);
            const uint4 b00 = __ldg((const uint4*)(gb1 + ob00 + zo1) + j);
            const uint4 b01 = __ldg((const uint4*)(gb1 + ob01 + zo1) + j);
            const uint4 b10 = __ldg((const uint4*)(gb1 + ob10 + zo1) + j);
            const uint4 b11 = __ldg((const uint4*)(gb1 + ob11 + zo1) + j);
            u64 v;
            v = xyz_interp(a00.x, a01.x, a10.x, a11.x, b00.x, b01.x, b10.x, b11.x,
                           w00h, w01h, w10h, w11h, wzq);
            hidp[0] = fma2q(v, sap[j], hidp[0]);
            v = xyz_interp(a00.y, a01.y, a10.y, a11.y, b00.y, b01.y, b10.y, b11.y,
                           w00h, w01h, w10h, w11h, wzq);
            hidp[1] = fma2q(v, sap[j], hidp[1]);
            v = xyz_interp(a00.z, a01.z, a10.z, a11.z, b00.z, b01.z, b10.z, b11.z,
                           w00h, w01h, w10h, w11h, wzq);
            hidp[2] = fma2q(v, sap[j], hidp[2]);
            v = xyz_interp(a00.w, a01.w, a10.w, a11.w, b00.w, b01.w, b10.w, b11.w,
                           w00h, w01h, w10h, w11h, wzq);
            hidp[3] = fma2q(v, sap[j], hidp[3]);
        }
    }
    float hid[8];
#pragma unroll
    for (int e = 0; e < 4; e++) {
        float lo, hi; upk2(lo, hi, hidp[e]);
        hid[2 * e]     = fmaxf(lo, 0.0f);
        hid[2 * e + 1] = fmaxf(hi, 0.0f);
    }

    // ---- guide NN #2 ----
    u64 hd[8];
#pragma unroll
    for (int q = 0; q < 8; q++) hd[q] = pk2(hid[q], hid[q]);
    float g2a = sb4s;
#pragma unroll
    for (int op = 0; op < 8; op++) {
        u64 t2 = *(const u64*)&b3p[op];
#pragma unroll
        for (int q = 0; q < 8; q++)
            t2 = fma2q(hd[q], *(const u64*)&sp3[op][q], t2);
        float lo, hi; upk2(lo, hi, t2);
        lo = fmaxf(lo, 0.0f); hi = fmaxf(hi, 0.0f);
        g2a = fmaf(sw4[2 * op], lo, g2a);
        g2a = fmaf(sw4[2 * op + 1], hi, g2a);
    }
    g2a = tanh_approx(g2a);

    // ---- z for slice 2 ----
    fz = fminf(fmaxf((g2a + 1.0f) * 3.5f, 0.0f), 7.0f);
    z0 = (int)fz;
    if (z0 > 7) z0 = 7;
    z1 = min(z0 + 1, 7);
    wzq = pk2(fz - (float)z0, fz - (float)z0);

    // ---- slice grid2 -> out[3] ----
    float m2[11];
#pragma unroll
    for (int q = 0; q < 8; q++) m2[q] = hid[q];
    m2[8] = 1.0f; m2[9] = 0.0f; m2[10] = 0.0f;

    float r[3] = {0.0f, 0.0f, 0.0f};
    {
        const __half* gb2 = g2h + pb * 65536;
        const int zo0 = z0 * 32, zo1 = z1 * 32;
#pragma unroll
        for (int j = 0; j < 4; j++) {
            const uint4 a00 = __ldg((const uint4*)(gb2 + ob00 + zo0) + j);
            const uint4 a01 = __ldg((const uint4*)(gb2 + ob01 + zo0) + j);
            const uint4 a10 = __ldg((const uint4*)(gb2 + ob10 + zo0) + j);
            const uint4 a11 = __ldg((const uint4*)(gb2 + ob11 + zo0) + j);
            const uint4 b00 = __ldg((const uint4*)(gb2 + ob00 + zo1) + j);
            const uint4 b01 = __ldg((const uint4*)(gb2 + ob01 + zo1) + j);
            const uint4 b10 = __ldg((const uint4*)(gb2 + ob10 + zo1) + j);
            const uint4 b11 = __ldg((const uint4*)(gb2 + ob11 + zo1) + j);
            float lo, hi;
            u64 v;
            {
                v = xyz_interp(a00.x, a01.x, a10.x, a11.x, b00.x, b01.x, b10.x, b11.x,
                               w00h, w01h, w10h, w11h, wzq);
                upk2(lo, hi, v);
                const int c = 8 * j;
                r[c % 3]       = fmaf(lo, m2[c / 3], r[c % 3]);
                r[(c + 1) % 3] = fmaf(hi, m2[(c + 1) / 3], r[(c + 1) % 3]);
            }
            {
                v = xyz_interp(a00.y, a01.y, a10.y, a11.y, b00.y, b01.y, b10.y, b11.y,
                               w00h, w01h, w10h, w11h, wzq);
                upk2(lo, hi, v);
                const int c = 8 * j + 2;
                r[c % 3]       = fmaf(lo, m2[c / 3], r[c % 3]);
                r[(c + 1) % 3] = fmaf(hi, m2[(c + 1) / 3], r[(c + 1) % 3]);
            }
            {
                v = xyz_interp(a00.z, a01.z, a10.z, a11.z, b00.z, b01.z, b10.z, b11.z,
                               w00h, w01h, w10h, w11h, wzq);
                upk2(lo, hi, v);
                const int c = 8 * j + 4;
                r[c % 3]       = fmaf(lo, m2[c / 3], r[c % 3]);
                r[(c + 1) % 3] = fmaf(hi, m2[(c + 1) / 3], r[(c + 1) % 3]);
            }
            {
                v = xyz_interp(a00.w, a01.w, a10.w, a11.w, b00.w, b01.w, b10.w, b11.w,
                               w00h, w01h, w10h, w11h, wzq);
                upk2(lo, hi, v);
                const int c = 8 * j + 6;
                r[c % 3]       = fmaf(lo, m2[c / 3], r[c % 3]);
                r[(c + 1) % 3] = fmaf(hi, m2[(c + 1) / 3], r[(c + 1) % 3]);
            }
        }
    }

    float* outp = out + (pb * 3) * HW + py * IMG_W + px;
    outp[0]      = r[0];
    outp[HW]     = r[1];
    outp[2 * HW] = r[2];
}

extern "C" void kernel_launch(void* const* d_in, const int* in_sizes, int n_in,
                              void* d_out, int out_size) {
    const float* src   = (const float*)d_in[0];
    const float* grid1 = (const float*)d_in[1];
    const float* grid2 = (const float*)d_in[2];
    const float* w1    = (const float*)d_in[3];
    const float* b1    = (const float*)d_in[4];
    const float* w2    = (const float*)d_in[5];
    const float* b2    = (const float*)d_in[6];
    const float* w3    = (const float*)d_in[7];
    const float* b3    = (const float*)d_in[8];
    const float* w4    = (const float*)d_in[9];
    const float* b4    = (const float*)d_in[10];
    float* out = (float*)d_out;

    {
        const int total = 8 * 32 * 8 * 256;
        transpose_grids_h<<<(total + 255) / 256, 256>>>(grid1, grid2);
    }
    const int total = 8 * IMG_H * IMG_W;
    bgrid_fused_kernel<<<total / 256, 256>>>(src,
                                             w1, b1, w2, b2, w3, b3, w4, b4,
                                             out);
}